// round 7
// baseline (speedup 1.0000x reference)
#include <cuda_runtime.h>
#include <cuda_bf16.h>
#include <math.h>

// ---------------------------------------------------------------------------
// GAT 2-layer pipeline, CSR gather formulation (all fp32 — fp16 H regressed:
// gathers are latency-bound, not bandwidth-bound).
// N=50000, E=800000 (+N self loops), L1: 4 heads x 32 (HT=128), L2: 1x64.
// ---------------------------------------------------------------------------

#define NMAX     50000
#define EMAX     800000
#define ETOTMAX  (EMAX + NMAX)

__device__ __align__(16) float g_H1[NMAX * 128];
__device__ __align__(16) float g_as1[NMAX * 4];
__device__ __align__(16) float g_ad1[NMAX * 4];
__device__ __align__(16) float g_out1[NMAX * 128];
__device__ __align__(16) float g_H2[NMAX * 64];
__device__ __align__(16) float g_as2[NMAX];
__device__ __align__(16) float g_ad2[NMAX];
__device__ int g_deg[NMAX];
__device__ int g_off[NMAX + 1];
__device__ int g_cursor[NMAX];
__device__ int g_csr_src[ETOTMAX];
__device__ int g_is64;

// ---------------------------------------------------------------------------
__global__ void detect_dtype_kernel(const int* __restrict__ ei32)
{
    int all_zero = 1;
    #pragma unroll
    for (int i = 1; i < 64; i += 2)
        if (ei32[i] != 0) all_zero = 0;
    g_is64 = all_zero;
}

__device__ __forceinline__ void edge_sd(const int* __restrict__ ei32,
                                        long long e, int E, int is64,
                                        int& s, int& d)
{
    if (e < E) {
        if (is64) { s = ei32[2 * e]; d = ei32[2 * ((long long)E + e)]; }
        else      { s = ei32[e];     d = ei32[(long long)E + e]; }
    } else {
        s = d = (int)(e - E);
    }
}

// ---------------------------------------------------------------------------
// CSR build — 4 edges per thread for MLP (count/fill are atomic-latency bound)
// ---------------------------------------------------------------------------
__global__ void count_kernel(const int* __restrict__ ei, int* __restrict__ deg,
                             int E, int N)
{
    int base = (blockIdx.x * blockDim.x + threadIdx.x) * 4;
    int etot = E + N;
    if (base >= etot) return;
    int is64 = g_is64;

    int d[4];
    if (base + 4 <= E) {
        if (!is64) {
            int4 v = *(const int4*)&ei[E + base];
            d[0] = v.x; d[1] = v.y; d[2] = v.z; d[3] = v.w;
        } else {
            const int2* p = (const int2*)ei;
            d[0] = p[(long long)E + base].x;
            d[1] = p[(long long)E + base + 1].x;
            d[2] = p[(long long)E + base + 2].x;
            d[3] = p[(long long)E + base + 3].x;
        }
        #pragma unroll
        for (int j = 0; j < 4; j++) atomicAdd(&deg[d[j]], 1);
    } else {
        for (int j = 0; j < 4; j++) {
            long long e = base + j;
            if (e >= etot) break;
            int s, dd;
            edge_sd(ei, e, E, is64, s, dd);
            atomicAdd(&deg[dd], 1);
        }
    }
}

// single-block fused scan: off = exclusive prefix, cursor = copy, off[n]=total
__global__ __launch_bounds__(1024) void scan_fused_kernel(
    const int* __restrict__ deg, int* __restrict__ off, int* __restrict__ cursor,
    int n, int total)
{
    const int C = (n + 1023) / 1024;
    int t = threadIdx.x;
    int lo = t * C;
    int hi = lo + C; if (hi > n) hi = n;
    if (lo > n) lo = n;

    int sum = 0;
    for (int i = lo; i < hi; i++) sum += deg[i];

    int lane = t & 31, wid = t >> 5;
    int x = sum;
    #pragma unroll
    for (int o = 1; o < 32; o <<= 1) {
        int y = __shfl_up_sync(0xffffffffu, x, o);
        if (lane >= o) x += y;
    }
    __shared__ int ws[32];
    if (lane == 31) ws[wid] = x;
    __syncthreads();
    if (wid == 0) {
        int v = ws[lane];
        #pragma unroll
        for (int o = 1; o < 32; o <<= 1) {
            int y = __shfl_up_sync(0xffffffffu, v, o);
            if (lane >= o) v += y;
        }
        ws[lane] = v;
    }
    __syncthreads();
    int base = (wid > 0 ? ws[wid - 1] : 0) + (x - sum);

    int run = base;
    for (int i = lo; i < hi; i++) {
        int d = deg[i];
        off[i] = run;
        cursor[i] = run;
        run += d;
    }
    if (t == 0) off[n] = total;
}

__global__ void fill_kernel(const int* __restrict__ ei, int* __restrict__ cursor,
                            int* __restrict__ csr_src, int E, int N)
{
    int base = (blockIdx.x * blockDim.x + threadIdx.x) * 4;
    int etot = E + N;
    if (base >= etot) return;
    int is64 = g_is64;

    if (base + 4 <= E) {
        int s[4], d[4];
        if (!is64) {
            int4 vs = *(const int4*)&ei[base];
            int4 vd = *(const int4*)&ei[E + base];
            s[0] = vs.x; s[1] = vs.y; s[2] = vs.z; s[3] = vs.w;
            d[0] = vd.x; d[1] = vd.y; d[2] = vd.z; d[3] = vd.w;
        } else {
            const int2* p = (const int2*)ei;
            #pragma unroll
            for (int j = 0; j < 4; j++) {
                s[j] = p[base + j].x;
                d[j] = p[(long long)E + base + j].x;
            }
        }
        #pragma unroll
        for (int j = 0; j < 4; j++) {
            int pos = atomicAdd(&cursor[d[j]], 1);
            csr_src[pos] = s[j];
        }
    } else {
        for (int j = 0; j < 4; j++) {
            long long e = base + j;
            if (e >= etot) break;
            int s, d;
            edge_sd(ei, e, E, is64, s, d);
            int pos = atomicAdd(&cursor[d], 1);
            csr_src[pos] = s;
        }
    }
}

// ---------------------------------------------------------------------------
// GEMM + fused asad epilogue (fp32 C).
// ---------------------------------------------------------------------------
template <int COLS, int HEADS>
__global__ __launch_bounds__(256) void gemm_asad_kernel(
    const float* __restrict__ A, const float* __restrict__ W,
    const float* __restrict__ att_s, const float* __restrict__ att_d,
    float* __restrict__ C, float* __restrict__ as_out, float* __restrict__ ad_out,
    int N)
{
    constexpr int K = 128;
    constexpr int MTILE = 64;
    constexpr int G = COLS / 4;
    constexpr int R = 256 / G;
    constexpr int RT = MTILE / R;
    constexpr int HID = COLS / HEADS;
    constexpr int RW = HID / 4;

    __shared__ float Xs[MTILE][K];

    const int tid = threadIdx.x;
    const int block_row = blockIdx.x * MTILE;

    #pragma unroll
    for (int i = tid; i < MTILE * (K / 4); i += 256) {
        int r = i / (K / 4);
        int c4 = i % (K / 4);
        int gr = block_row + r;
        float4 v = make_float4(0.f, 0.f, 0.f, 0.f);
        if (gr < N) v = ((const float4*)A)[(size_t)gr * (K / 4) + c4];
        *(float4*)&Xs[r][c4 * 4] = v;
    }
    __syncthreads();

    const int cg = tid % G;
    const int rg = tid / G;

    float acc[RT][4];
    #pragma unroll
    for (int r = 0; r < RT; r++) {
        acc[r][0] = 0.f; acc[r][1] = 0.f; acc[r][2] = 0.f; acc[r][3] = 0.f;
    }

    #pragma unroll 4
    for (int k = 0; k < K; k++) {
        float4 w = ((const float4*)W)[k * G + cg];
        #pragma unroll
        for (int r = 0; r < RT; r++) {
            float a = Xs[rg * RT + r][k];
            acc[r][0] = fmaf(a, w.x, acc[r][0]);
            acc[r][1] = fmaf(a, w.y, acc[r][1]);
            acc[r][2] = fmaf(a, w.z, acc[r][2]);
            acc[r][3] = fmaf(a, w.w, acc[r][3]);
        }
    }

    const float4 ws = ((const float4*)att_s)[cg];
    const float4 wd = ((const float4*)att_d)[cg];

    #pragma unroll
    for (int r = 0; r < RT; r++) {
        int gr = block_row + rg * RT + r;
        if (gr < N)
            ((float4*)C)[(size_t)gr * G + cg] =
                make_float4(acc[r][0], acc[r][1], acc[r][2], acc[r][3]);

        float ps = acc[r][0] * ws.x + acc[r][1] * ws.y + acc[r][2] * ws.z + acc[r][3] * ws.w;
        float pd = acc[r][0] * wd.x + acc[r][1] * wd.y + acc[r][2] * wd.z + acc[r][3] * wd.w;
        #pragma unroll
        for (int o = RW / 2; o > 0; o >>= 1) {
            ps += __shfl_xor_sync(0xffffffffu, ps, o);
            pd += __shfl_xor_sync(0xffffffffu, pd, o);
        }
        if ((cg % RW) == 0 && gr < N) {
            int head = cg / RW;
            as_out[gr * HEADS + head] = ps;
            ad_out[gr * HEADS + head] = pd;
        }
    }
}

// ---------------------------------------------------------------------------
// Fused softmax + aggregation, gather form. One warp per dst node.
// gather128: unroll 8 for MLP (latency-bound loop).
// ---------------------------------------------------------------------------
__global__ __launch_bounds__(256) void gather128_kernel(
    const int* __restrict__ off, const int* __restrict__ csr_src,
    const float* __restrict__ H,
    const float* __restrict__ as_, const float* __restrict__ ad_,
    const float* __restrict__ bias,
    float* __restrict__ out, int N)
{
    int w = (blockIdx.x * blockDim.x + threadIdx.x) >> 5;
    int lane = threadIdx.x & 31;
    if (w >= N) return;
    int n = w;
    int h = lane >> 3;

    const float ad_v = ad_[n * 4 + h];
    int beg = off[n], end = off[n + 1];
    const float4* __restrict__ H4 = (const float4*)H;

    float4 acc = make_float4(0.f, 0.f, 0.f, 0.f);
    float dsum = 0.f;

    int k = beg;
    for (; k + 8 <= end; k += 8) {
        int s[8]; float a[8]; float4 hv[8];
        #pragma unroll
        for (int i = 0; i < 8; i++) s[i] = csr_src[k + i];
        #pragma unroll
        for (int i = 0; i < 8; i++) a[i] = as_[s[i] * 4 + h];
        #pragma unroll
        for (int i = 0; i < 8; i++) hv[i] = H4[(size_t)s[i] * 32 + lane];
        #pragma unroll
        for (int i = 0; i < 8; i++) {
            float v = a[i] + ad_v;
            v = v > 0.f ? v : 0.2f * v;
            float ex = __expf(v);
            dsum += ex;
            acc.x = fmaf(ex, hv[i].x, acc.x);
            acc.y = fmaf(ex, hv[i].y, acc.y);
            acc.z = fmaf(ex, hv[i].z, acc.z);
            acc.w = fmaf(ex, hv[i].w, acc.w);
        }
    }
    for (; k + 4 <= end; k += 4) {
        int s[4]; float a[4]; float4 hv[4];
        #pragma unroll
        for (int i = 0; i < 4; i++) s[i] = csr_src[k + i];
        #pragma unroll
        for (int i = 0; i < 4; i++) a[i] = as_[s[i] * 4 + h];
        #pragma unroll
        for (int i = 0; i < 4; i++) hv[i] = H4[(size_t)s[i] * 32 + lane];
        #pragma unroll
        for (int i = 0; i < 4; i++) {
            float v = a[i] + ad_v;
            v = v > 0.f ? v : 0.2f * v;
            float ex = __expf(v);
            dsum += ex;
            acc.x = fmaf(ex, hv[i].x, acc.x);
            acc.y = fmaf(ex, hv[i].y, acc.y);
            acc.z = fmaf(ex, hv[i].z, acc.z);
            acc.w = fmaf(ex, hv[i].w, acc.w);
        }
    }
    for (; k < end; k++) {
        int s = csr_src[k];
        float v = as_[s * 4 + h] + ad_v;
        v = v > 0.f ? v : 0.2f * v;
        float ex = __expf(v);
        dsum += ex;
        float4 hv = H4[(size_t)s * 32 + lane];
        acc.x = fmaf(ex, hv.x, acc.x);
        acc.y = fmaf(ex, hv.y, acc.y);
        acc.z = fmaf(ex, hv.z, acc.z);
        acc.w = fmaf(ex, hv.w, acc.w);
    }

    float inv = 1.0f / dsum;
    float4 b = ((const float4*)bias)[lane];
    float4 r;
    r.x = acc.x * inv + b.x;
    r.y = acc.y * inv + b.y;
    r.z = acc.z * inv + b.z;
    r.w = acc.w * inv + b.w;
    r.x = r.x > 0.f ? r.x : expm1f(r.x);
    r.y = r.y > 0.f ? r.y : expm1f(r.y);
    r.z = r.z > 0.f ? r.z : expm1f(r.z);
    r.w = r.w > 0.f ? r.w : expm1f(r.w);
    ((float4*)out)[(size_t)n * 32 + lane] = r;
}

// Layer 2: one warp per node; lane owns float2 channels (R5-proven shape).
__global__ __launch_bounds__(256) void gather64_kernel(
    const int* __restrict__ off, const int* __restrict__ csr_src,
    const float* __restrict__ H,
    const float* __restrict__ as_, const float* __restrict__ ad_,
    const float* __restrict__ bias,
    float* __restrict__ out, int N)
{
    int w = (blockIdx.x * blockDim.x + threadIdx.x) >> 5;
    int lane = threadIdx.x & 31;
    if (w >= N) return;
    int n = w;

    const float ad_v = ad_[n];
    int beg = off[n], end = off[n + 1];
    const float2* __restrict__ H2 = (const float2*)H;

    float2 acc = make_float2(0.f, 0.f);
    float dsum = 0.f;

    int k = beg;
    for (; k + 8 <= end; k += 8) {
        int s[8]; float a[8]; float2 hv[8];
        #pragma unroll
        for (int i = 0; i < 8; i++) s[i] = csr_src[k + i];
        #pragma unroll
        for (int i = 0; i < 8; i++) a[i] = as_[s[i]];
        #pragma unroll
        for (int i = 0; i < 8; i++) hv[i] = H2[(size_t)s[i] * 32 + lane];
        #pragma unroll
        for (int i = 0; i < 8; i++) {
            float v = a[i] + ad_v;
            v = v > 0.f ? v : 0.2f * v;
            float ex = __expf(v);
            dsum += ex;
            acc.x = fmaf(ex, hv[i].x, acc.x);
            acc.y = fmaf(ex, hv[i].y, acc.y);
        }
    }
    for (; k < end; k++) {
        int s = csr_src[k];
        float v = as_[s] + ad_v;
        v = v > 0.f ? v : 0.2f * v;
        float ex = __expf(v);
        dsum += ex;
        float2 hv = H2[(size_t)s * 32 + lane];
        acc.x = fmaf(ex, hv.x, acc.x);
        acc.y = fmaf(ex, hv.y, acc.y);
    }

    float inv = 1.0f / dsum;
    float2 b = ((const float2*)bias)[lane];
    float2 r;
    r.x = acc.x * inv + b.x;
    r.y = acc.y * inv + b.y;
    ((float2*)out)[(size_t)n * 32 + lane] = r;
}

// ---------------------------------------------------------------------------
// launch
// ---------------------------------------------------------------------------
extern "C" void kernel_launch(void* const* d_in, const int* in_sizes, int n_in,
                              void* d_out, int out_size)
{
    const float* x    = (const float*)d_in[0];
    const int*   ei   = (const int*)d_in[1];
    const float* W1   = (const float*)d_in[2];
    const float* as1w = (const float*)d_in[3];
    const float* ad1w = (const float*)d_in[4];
    const float* b1   = (const float*)d_in[5];
    const float* W2   = (const float*)d_in[6];
    const float* as2w = (const float*)d_in[7];
    const float* ad2w = (const float*)d_in[8];
    const float* b2   = (const float*)d_in[9];
    float* out = (float*)d_out;

    const int N = in_sizes[0] / 128;   // 50000
    const int E = in_sizes[1] / 2;     // 800000
    const int ETOT = E + N;

    float *H1, *as1, *ad1, *out1, *H2, *as2, *ad2;
    int *deg, *off, *cursor, *csr_src;
    cudaGetSymbolAddress((void**)&H1, g_H1);
    cudaGetSymbolAddress((void**)&as1, g_as1);
    cudaGetSymbolAddress((void**)&ad1, g_ad1);
    cudaGetSymbolAddress((void**)&out1, g_out1);
    cudaGetSymbolAddress((void**)&H2, g_H2);
    cudaGetSymbolAddress((void**)&as2, g_as2);
    cudaGetSymbolAddress((void**)&ad2, g_ad2);
    cudaGetSymbolAddress((void**)&deg, g_deg);
    cudaGetSymbolAddress((void**)&off, g_off);
    cudaGetSymbolAddress((void**)&cursor, g_cursor);
    cudaGetSymbolAddress((void**)&csr_src, g_csr_src);

    detect_dtype_kernel<<<1, 1>>>(ei);

    // ---------- CSR build ----------
    cudaMemsetAsync(deg, 0, N * sizeof(int));
    {
        int groups = (ETOT + 3) / 4;
        count_kernel<<<(groups + 255) / 256, 256>>>(ei, deg, E, N);
        scan_fused_kernel<<<1, 1024>>>(deg, off, cursor, N, ETOT);
        fill_kernel<<<(groups + 255) / 256, 256>>>(ei, cursor, csr_src, E, N);
    }

    // ---------- Layer 1 (HT=128, 4 heads) ----------
    gemm_asad_kernel<128, 4><<<(N + 63) / 64, 256>>>(x, W1, as1w, ad1w, H1, as1, ad1, N);
    gather128_kernel<<<(N + 7) / 8, 256>>>(off, csr_src, H1, as1, ad1, b1, out1, N);

    // ---------- Layer 2 (HT=64, 1 head) ----------
    gemm_asad_kernel<64, 1><<<(N + 63) / 64, 256>>>(out1, W2, as2w, ad2w, H2, as2, ad2, N);
    gather64_kernel<<<(N + 7) / 8, 256>>>(off, csr_src, H2, as2, ad2, b2, out, N);
}